// round 5
// baseline (speedup 1.0000x reference)
#include <cuda_runtime.h>
#include <cstdint>

#define Bq 8
#define Lq 256
#define Hq 128
#define BLq 2048
#define HHq 16384

// ---------------- scratch (no allocation allowed) ----------------
__device__ float g_qln[BLq*Hq];
__device__ float g_Q  [BLq*Hq];
__device__ float g_K  [BLq*Hq];
__device__ float g_V  [BLq*Hq];
__device__ float g_u  [BLq*4*Hq];
__device__ float g_att[BLq*Hq];
__device__ float g_x  [BLq*Hq];

// ---------------- helpers ----------------
__device__ __forceinline__ void cpa16(float* s, const float* g){
    unsigned sa = (unsigned)__cvta_generic_to_shared(s);
    asm volatile("cp.async.cg.shared.global [%0], [%1], 16;\n" :: "r"(sa), "l"(g));
}

// ---------------- final layernorm ----------------
__global__ void k_ln(const float* __restrict__ x, const float* __restrict__ g,
                     const float* __restrict__ bb, float* __restrict__ y){
    int r = blockIdx.x; int e = threadIdx.x;
    float v = x[(size_t)r*Hq + e];
    float s = v, s2 = v*v;
    #pragma unroll
    for(int o=16;o;o>>=1){
        s  += __shfl_xor_sync(0xffffffffu, s , o);
        s2 += __shfl_xor_sync(0xffffffffu, s2, o);
    }
    __shared__ float sh[8];
    int w = e>>5, l = e&31;
    if(l==0){ sh[w]=s; sh[4+w]=s2; }
    __syncthreads();
    s  = sh[0]+sh[1]+sh[2]+sh[3];
    s2 = sh[4]+sh[5]+sh[6]+sh[7];
    float m   = s * (1.0f/128.0f);
    float var = s2 * (1.0f/128.0f) - m*m;
    y[(size_t)r*Hq + e] = (v - m) * rsqrtf(var + 1e-8f) * g[e] + bb[e];
}

// ---------------- in-smem LN of a 16x128 row tile (8 warps, 2 rows each) ------
__device__ __forceinline__ void ln16(float xs[16][128], const float* __restrict__ g,
                                     const float* __restrict__ bb, int w, int l,
                                     float* __restrict__ sideout, int r0){
    #pragma unroll
    for(int rs=0;rs<2;rs++){
        int rr = w + rs*8;
        float v0=xs[rr][l], v1=xs[rr][l+32], v2=xs[rr][l+64], v3=xs[rr][l+96];
        float s  = v0+v1+v2+v3;
        float s2 = v0*v0+v1*v1+v2*v2+v3*v3;
        #pragma unroll
        for(int o=16;o;o>>=1){
            s  += __shfl_xor_sync(0xffffffffu, s , o);
            s2 += __shfl_xor_sync(0xffffffffu, s2, o);
        }
        float m   = s * (1.0f/128.0f);
        float inv = rsqrtf(s2*(1.0f/128.0f) - m*m + 1e-8f);
        float o0 = (v0-m)*inv*g[l]    + bb[l];
        float o1 = (v1-m)*inv*g[l+32] + bb[l+32];
        float o2 = (v2-m)*inv*g[l+64] + bb[l+64];
        float o3 = (v3-m)*inv*g[l+96] + bb[l+96];
        xs[rr][l]=o0; xs[rr][l+32]=o1; xs[rr][l+64]=o2; xs[rr][l+96]=o3;
        if(sideout){
            float* dst = sideout + (size_t)(r0+rr)*Hq;
            dst[l]=o0; dst[l+32]=o1; dst[l+64]=o2; dst[l+96]=o3;
        }
    }
}

// ---------------- 16-row tiled GEMM helper ----------------
__device__ __forceinline__ void mat16(const float xs[16][128], float ps[16][128],
                                      const float* __restrict__ W, const float* __restrict__ bias,
                                      int e, int s, float out[16]){
    float acc[16];
    #pragma unroll
    for(int r=0;r<16;r++) acc[r]=0.f;
    const float4* wq = (const float4*)(W + (size_t)e*128 + s*64);
    #pragma unroll
    for(int cq=0;cq<16;cq++){
        float4 wv = wq[cq];
        #pragma unroll
        for(int r=0;r<16;r++){
            float4 xv = *(const float4*)(&xs[r][s*64 + cq*4]);
            acc[r] += wv.x*xv.x + wv.y*xv.y + wv.z*xv.z + wv.w*xv.w;
        }
    }
    if(s==1){
        #pragma unroll
        for(int r=0;r<16;r++) ps[r][e]=acc[r];
    }
    __syncthreads();
    if(s==0){
        float be = bias[e];
        #pragma unroll
        for(int r=0;r<16;r++) out[r] = acc[r] + ps[r][e] + be;
    }
}

// ---------------- k_proj: LN1 fused + Q,K,V + u = WA1_h^T Q_h ----------------
__global__ void __launch_bounds__(256) k_proj(
    const float* __restrict__ xin,
    const float* __restrict__ g1, const float* __restrict__ b1,
    const float* __restrict__ Wq, const float* __restrict__ bq,
    const float* __restrict__ Wk, const float* __restrict__ bk,
    const float* __restrict__ Wv, const float* __restrict__ bv,
    const float* __restrict__ Wa1,
    float* __restrict__ qlno,
    float* __restrict__ Qo, float* __restrict__ Ko, float* __restrict__ Vo,
    float* __restrict__ uo)
{
    __shared__ float xs[16][128];
    __shared__ float ps[16][128];
    __shared__ float Qs[16][128];
    int t = threadIdx.x; int e = t & 127; int s = t >> 7;
    int l = t & 31;    int w = t >> 5;
    int r0 = blockIdx.x * 16;
    for(int k=t;k<2048;k+=256) xs[k>>7][k&127] = xin[(size_t)r0*Hq + k];
    __syncthreads();
    ln16(xs, g1, b1, w, l, qlno, r0);
    __syncthreads();

    float o16[16];
    mat16(xs, ps, Wq, bq, e, s, o16);
    if(s==0){
        #pragma unroll
        for(int r=0;r<16;r++){ float v=o16[r]; Qo[(size_t)(r0+r)*Hq+e]=v; Qs[r][e]=v; }
    }
    __syncthreads();
    mat16(xs, ps, Wk, bk, e, s, o16);
    if(s==0){
        #pragma unroll
        for(int r=0;r<16;r++) Ko[(size_t)(r0+r)*Hq+e]=o16[r];
    }
    __syncthreads();
    mat16(xs, ps, Wv, bv, e, s, o16);
    if(s==0){
        #pragma unroll
        for(int r=0;r<16;r++) Vo[(size_t)(r0+r)*Hq+e]=o16[r];
    }
    __syncthreads();

    // u[row][h][c] = sum_d WA1[h*32+d, c] * Q[row, h*32+d]
    int h = t>>6, c0 = t&63;
    float a0[16], a1[16];
    #pragma unroll
    for(int r=0;r<16;r++){ a0[r]=0.f; a1[r]=0.f; }
    for(int d=0; d<32; d++){
        const float* wr = Wa1 + (size_t)(h*32+d)*128;
        float w0 = wr[c0], w1 = wr[c0+64];
        #pragma unroll
        for(int r=0;r<16;r++){
            float q = Qs[r][h*32+d];
            a0[r] += w0*q; a1[r] += w1*q;
        }
    }
    #pragma unroll
    for(int r=0;r<16;r++){
        size_t base = ((size_t)(r0+r)*4 + h)*128;
        uo[base + c0]      = a0[r];
        uo[base + c0 + 64] = a1[r];
    }
}

// ---------------- fused flash-style attention: one CTA per (b,i) ----------------
// smem: buf 2x(64x128) | sc_raw 256 | sc_w 256 | t_s 512 | alph 4 | sinv 4
#define ATTN_FLOATS (16384 + 256 + 256 + 512 + 8)
#define ATTN_SMEM (ATTN_FLOATS*4)
__global__ void __launch_bounds__(256) k_attn(
    const float* __restrict__ tm,  const float* __restrict__ qln,
    const float* __restrict__ Qp,  const float* __restrict__ Kp,
    const float* __restrict__ Vp,  const float* __restrict__ up,
    const unsigned char* __restrict__ msk,
    const float* __restrict__ Wa2, float* __restrict__ xo)
{
    extern __shared__ float sm[];
    float* sc_raw = sm + 16384;
    float* sc_w   = sm + 16640;
    float* t_s    = sm + 16896;
    float* alph   = sm + 17408;
    float* sinv   = sm + 17412;

    int t = threadIdx.x, l = t&31, w = t>>5;
    int r = blockIdx.x, b = r>>8;
    int i = 255 - (r & 255);          // big rows first (tail balance)
    int rr = (b<<8) + i;
    bool rowmask = msk[rr] != 0;
    int nj  = rowmask ? 256 : (i+1);
    int nch = (nj + 63) >> 6;

    // issue chunk 0
    {
        float* dst = sm;
        int jn = nj < 64 ? nj : 64;
        const float* src = tm + (size_t)rr*32768;
        int n4 = jn*32;
        for(int k=t;k<n4;k+=256) cpa16(dst + 4*k, src + 4*k);
        int padf = (64-jn)*128;
        for(int k=t;k<padf;k+=256) dst[jn*128+k]=0.f;
    }
    asm volatile("cp.async.commit_group;\n"::);

    // preload per-row vectors (overlaps with cp.async)
    float4 uv0,uv1,uv2,uv3; float qv0,qv1,qv2,qv3;
    {
        const float4* ub = (const float4*)(up + (size_t)rr*512);
        uv0 = ub[l]; uv1 = ub[32+l]; uv2 = ub[64+l]; uv3 = ub[96+l];
        const float* Qr = Qp + (size_t)rr*128;
        qv0 = Qr[l]; qv1 = Qr[32+l]; qv2 = Qr[64+l]; qv3 = Qr[96+l];
    }

    float tA=0.f, tB=0.f, oA=0.f;
    const float NINF = -3.402823466e38f;
    const float NEGV = -4294967295.0f;
    float m_run = NINF, s_run = 0.f;
    int hT = t>>7, cT = t&127;          // t-accumulator ownership
    int eO = t & 127, hO = eO>>5;       // o-accumulator ownership (t<128)

    for(int c=0;c<nch;c++){
        if(c+1 < nch){
            float* dst = sm + ((c+1)&1)*8192;
            int j0n = (c+1)<<6;
            int jn = nj - j0n; if(jn>64) jn=64;
            const float* src = tm + (size_t)rr*32768 + (size_t)j0n*128;
            int n4 = jn*32;
            for(int k=t;k<n4;k+=256) cpa16(dst + 4*k, src + 4*k);
            int padf = (64-jn)*128;
            for(int k=t;k<padf;k+=256) dst[jn*128+k]=0.f;
            asm volatile("cp.async.commit_group;\n"::);
            asm volatile("cp.async.wait_group 1;\n"::);
        } else {
            asm volatile("cp.async.wait_group 0;\n"::);
        }
        __syncthreads();
        const float* bufc = sm + (c&1)*8192;
        int j0 = c<<6;

        // ---- phase A: raw scores (warp per j) ----
        #pragma unroll
        for(int jj=w; jj<64; jj+=8){
            float4 tv = ((const float4*)(bufc + jj*128))[l];
            const float* Kr = Kp + (((size_t)b<<8) + (j0+jj))*128;
            float a0 = uv0.x*tv.x + uv0.y*tv.y + uv0.z*tv.z + uv0.w*tv.w + qv0*Kr[l];
            float a1 = uv1.x*tv.x + uv1.y*tv.y + uv1.z*tv.z + uv1.w*tv.w + qv1*Kr[32+l];
            float a2 = uv2.x*tv.x + uv2.y*tv.y + uv2.z*tv.z + uv2.w*tv.w + qv2*Kr[64+l];
            float a3 = uv3.x*tv.x + uv3.y*tv.y + uv3.z*tv.z + uv3.w*tv.w + qv3*Kr[96+l];
            #pragma unroll
            for(int o=16;o;o>>=1){
                a0 += __shfl_xor_sync(0xffffffffu,a0,o);
                a1 += __shfl_xor_sync(0xffffffffu,a1,o);
                a2 += __shfl_xor_sync(0xffffffffu,a2,o);
                a3 += __shfl_xor_sync(0xffffffffu,a3,o);
            }
            if(l<4) sc_raw[l*64 + jj] = (l==0)?a0:((l==1)?a1:((l==2)?a2:a3));
        }
        __syncthreads();

        // ---- phase B: online softmax update (warp w = head w) ----
        if(w<4){
            float s0 = sc_raw[w*64 + l]      * 0.17677669529663689f;
            float s1 = sc_raw[w*64 + 32 + l] * 0.17677669529663689f;
            bool v0 = ((j0 + l)      < nj) && !rowmask;
            bool v1 = ((j0 + 32 + l) < nj) && !rowmask;
            s0 = v0 ? s0 : NEGV;
            s1 = v1 ? s1 : NEGV;
            float mx = fmaxf(s0, s1);
            #pragma unroll
            for(int o=16;o;o>>=1) mx = fmaxf(mx, __shfl_xor_sync(0xffffffffu,mx,o));
            float mnew = fmaxf(m_run, mx);
            float alpha = __expf(m_run - mnew);
            float e0 = __expf(s0 - mnew), e1 = __expf(s1 - mnew);
            float cs = e0 + e1;
            #pragma unroll
            for(int o=16;o;o>>=1) cs += __shfl_xor_sync(0xffffffffu,cs,o);
            s_run = s_run*alpha + cs;
            m_run = mnew;
            sc_w[w*64 + l]      = e0;
            sc_w[w*64 + 32 + l] = e1;
            if(l==0) alph[w] = alpha;
        }
        __syncthreads();

        // ---- phase C: rescale + accumulate t and o ----
        {
            float aA = alph[hT], aB = alph[hT+2];
            tA *= aA; tB *= aB;
            const float4* wa4 = (const float4*)(sc_w + hT*64);
            const float4* wb4 = (const float4*)(sc_w + (hT+2)*64);
            const float* bp = bufc + cT;
            #pragma unroll 4
            for(int jq=0;jq<16;jq++){
                float4 wa = wa4[jq], wb = wb4[jq];
                const float* tp = bp + jq*512;
                float t0=tp[0], t1=tp[128], t2=tp[256], t3=tp[384];
                tA += wa.x*t0 + wa.y*t1 + wa.z*t2 + wa.w*t3;
                tB += wb.x*t0 + wb.y*t1 + wb.z*t2 + wb.w*t3;
            }
        }
        if(t<128){
            oA *= alph[hO];
            const float4* wr4 = (const float4*)(sc_w + hO*64);
            const float* Vb = Vp + ((((size_t)b<<8) + j0))*128 + eO;
            #pragma unroll 4
            for(int jq=0;jq<16;jq++){
                float4 ww = wr4[jq];
                const float* vp = Vb + jq*512;
                oA += ww.x*vp[0] + ww.y*vp[128] + ww.z*vp[256] + ww.w*vp[384];
            }
        }
        __syncthreads();
    }

    if(w<4 && l==0) sinv[w] = 1.0f / s_run;
    __syncthreads();
    t_s[hT*128 + cT]     = tA * sinv[hT];
    t_s[(hT+2)*128 + cT] = tB * sinv[hT+2];
    __syncthreads();
    if(t<128){
        float acc = oA * sinv[hO];
        const float4* w2 = (const float4*)(Wa2 + (size_t)eO*128);
        const float4* th = (const float4*)(t_s + hO*128);
        #pragma unroll
        for(int cq=0;cq<32;cq++){
            float4 a=w2[cq], tv=th[cq];
            acc += a.x*tv.x + a.y*tv.y + a.z*tv.z + a.w*tv.w;
        }
        xo[(size_t)rr*128 + eO] = qln[(size_t)rr*128 + eO] + acc;
    }
}

// ---------------- k_ffn: LN2 fused + relu(x@W1^T+b1)@W2^T + b2 + x, * keep ----
__global__ void __launch_bounds__(256) k_ffn(
    const float* __restrict__ attin,
    const float* __restrict__ g2, const float* __restrict__ b2g,
    const float* __restrict__ W1, const float* __restrict__ b1,
    const float* __restrict__ W2, const float* __restrict__ b2,
    const unsigned char* __restrict__ msk, float* __restrict__ xo)
{
    __shared__ float xs[16][128];
    __shared__ float ps[16][128];
    __shared__ float hs[16][128];
    int t = threadIdx.x; int e = t & 127; int s = t >> 7;
    int l = t & 31;    int w = t >> 5;
    int r0 = blockIdx.x * 16;
    for(int k=t;k<2048;k+=256) xs[k>>7][k&127] = attin[(size_t)r0*Hq + k];
    __syncthreads();
    ln16(xs, g2, b2g, w, l, (float*)0, r0);
    __syncthreads();

    float o16[16];
    mat16(xs, ps, W1, b1, e, s, o16);
    if(s==0){
        #pragma unroll
        for(int r=0;r<16;r++) hs[r][e] = fmaxf(o16[r], 0.f);
    }
    __syncthreads();
    mat16(hs, ps, W2, b2, e, s, o16);
    if(s==0){
        #pragma unroll
        for(int r=0;r<16;r++){
            int row = r0 + r;
            float kp = msk[row] ? 0.f : 1.f;
            xo[(size_t)row*Hq + e] = (o16[r] + xs[r][e]) * kp;
        }
    }
}

// ---------------- launch ----------------
extern "C" void kernel_launch(void* const* d_in, const int* in_sizes, int n_in,
                              void* d_out, int out_size){
    const float* seqs = (const float*)d_in[0];
    const unsigned char* msk = (const unsigned char*)d_in[1];
    const float* tm  = (const float*)d_in[2];
    const float* Qw  = (const float*)d_in[3];
    const float* Qb  = (const float*)d_in[4];
    const float* Kw  = (const float*)d_in[5];
    const float* Kb  = (const float*)d_in[6];
    const float* Vw  = (const float*)d_in[7];
    const float* Vb  = (const float*)d_in[8];
    const float* WA1 = (const float*)d_in[9];
    const float* WA2 = (const float*)d_in[10];
    const float* ln1g= (const float*)d_in[11];
    const float* ln1b= (const float*)d_in[12];
    const float* ln2g= (const float*)d_in[13];
    const float* ln2b= (const float*)d_in[14];
    const float* c1w = (const float*)d_in[15];
    const float* c1b = (const float*)d_in[16];
    const float* c2w = (const float*)d_in[17];
    const float* c2b = (const float*)d_in[18];
    const float* lnfg= (const float*)d_in[19];
    const float* lnfb= (const float*)d_in[20];

    float *gqln,*gQ,*gK,*gV,*gu,*gatt,*gx;
    cudaGetSymbolAddress((void**)&gqln, g_qln);
    cudaGetSymbolAddress((void**)&gQ,   g_Q);
    cudaGetSymbolAddress((void**)&gK,   g_K);
    cudaGetSymbolAddress((void**)&gV,   g_V);
    cudaGetSymbolAddress((void**)&gu,   g_u);
    cudaGetSymbolAddress((void**)&gatt, g_att);
    cudaGetSymbolAddress((void**)&gx,   g_x);

    cudaFuncSetAttribute(k_attn, cudaFuncAttributeMaxDynamicSharedMemorySize, ATTN_SMEM);

    for(int blk=0; blk<2; blk++){
        const float* xin = blk ? (const float*)gx : seqs;
        k_proj<<<128,256>>>(xin, ln1g+blk*Hq, ln1b+blk*Hq,
                            Qw+(size_t)blk*HHq, Qb+blk*Hq,
                            Kw+(size_t)blk*HHq, Kb+blk*Hq,
                            Vw+(size_t)blk*HHq, Vb+blk*Hq,
                            WA1+(size_t)blk*HHq,
                            gqln, gQ, gK, gV, gu);
        k_attn<<<BLq,256,ATTN_SMEM>>>(tm, gqln, gQ, gK, gV, gu, msk,
                                      WA2+(size_t)blk*HHq, gatt);
        k_ffn <<<128,256>>>(gatt, ln2g+blk*Hq, ln2b+blk*Hq,
                            c1w+(size_t)blk*HHq, c1b+blk*Hq,
                            c2w+(size_t)blk*HHq, c2b+blk*Hq, msk, gx);
    }
    k_ln<<<BLq,128>>>(gx, lnfg, lnfb, (float*)d_out);
}

// round 6
// speedup vs baseline: 1.5170x; 1.5170x over previous
#include <cuda_runtime.h>
#include <cstdint>

#define Hq 128
#define BLq 2048
#define HHq 16384

// ---------------- scratch ----------------
__device__ float g_qln[BLq*Hq];
__device__ float g_Q  [BLq*Hq];
__device__ float g_K  [BLq*Hq];
__device__ float g_V  [BLq*Hq];
__device__ float g_u  [BLq*4*Hq];
__device__ float g_qk [BLq*4*256];
__device__ float g_att[BLq*Hq];
__device__ float g_x  [BLq*Hq];

// ---------------- helpers ----------------
__device__ __forceinline__ void cpa16(float* s, const float* g){
    unsigned sa = (unsigned)__cvta_generic_to_shared(s);
    asm volatile("cp.async.cg.shared.global [%0], [%1], 16;\n" :: "r"(sa), "l"(g));
}
__device__ __forceinline__ void ffma2(unsigned long long &acc, unsigned long long a, unsigned long long b){
    asm("fma.rn.f32x2 %0, %1, %2, %0;" : "+l"(acc) : "l"(a), "l"(b));
}
__device__ __forceinline__ float ullsum(unsigned long long v){
    float lo,hi; asm("mov.b64 {%0,%1}, %2;" : "=f"(lo), "=f"(hi) : "l"(v));
    return lo+hi;
}

// per-warp LN of one 128-float smem row (writes back; optional global copy)
__device__ __forceinline__ void lnrow(float* row, const float* __restrict__ g,
                                      const float* __restrict__ bb, int l,
                                      float* __restrict__ gout){
    float v0=row[l], v1=row[l+32], v2=row[l+64], v3=row[l+96];
    float s  = v0+v1+v2+v3;
    float s2 = v0*v0+v1*v1+v2*v2+v3*v3;
    #pragma unroll
    for(int o=16;o;o>>=1){
        s  += __shfl_xor_sync(0xffffffffu, s , o);
        s2 += __shfl_xor_sync(0xffffffffu, s2, o);
    }
    float m   = s * (1.0f/128.0f);
    float inv = rsqrtf(s2*(1.0f/128.0f) - m*m + 1e-8f);
    float o0 = (v0-m)*inv*g[l]    + bb[l];
    float o1 = (v1-m)*inv*g[l+32] + bb[l+32];
    float o2 = (v2-m)*inv*g[l+64] + bb[l+64];
    float o3 = (v3-m)*inv*g[l+96] + bb[l+96];
    row[l]=o0; row[l+32]=o1; row[l+64]=o2; row[l+96]=o3;
    if(gout){ gout[l]=o0; gout[l+32]=o1; gout[l+64]=o2; gout[l+96]=o3; }
}

// ---- 16-row GEMM tile, 512 threads, K split in 4 quarters (e=t&127, s=t>>7) ----
__device__ __forceinline__ void mat16q(const float (*xs)[128], float (*ps)[16][128],
                                       const float* __restrict__ W, const float* __restrict__ bias,
                                       int e, int s, float out[16]){
    unsigned long long acc[16];
    #pragma unroll
    for(int r=0;r<16;r++) acc[r]=0ULL;
    const float* wp = W + (size_t)e*128 + s*32;
    #pragma unroll
    for(int cq=0;cq<8;cq++){
        ulonglong2 wv = *(const ulonglong2*)(wp + cq*4);
        #pragma unroll
        for(int r=0;r<16;r++){
            ulonglong2 xv = *(const ulonglong2*)(&xs[r][s*32 + cq*4]);
            ffma2(acc[r], wv.x, xv.x);
            ffma2(acc[r], wv.y, xv.y);
        }
    }
    float a[16];
    #pragma unroll
    for(int r=0;r<16;r++) a[r] = ullsum(acc[r]);
    if(s>0){
        #pragma unroll
        for(int r=0;r<16;r++) ps[s-1][r][e]=a[r];
    }
    __syncthreads();
    if(s==0){
        float be = bias[e];
        #pragma unroll
        for(int r=0;r<16;r++) out[r] = a[r] + ps[0][r][e] + ps[1][r][e] + ps[2][r][e] + be;
    }
    __syncthreads();
}

// ---------------- k_proj: LN1 + Q,K,V + u = WA1_h^T Q_h ----------------
__global__ void __launch_bounds__(512) k_proj(
    const float* __restrict__ xin,
    const float* __restrict__ g1, const float* __restrict__ b1,
    const float* __restrict__ Wq, const float* __restrict__ bq,
    const float* __restrict__ Wk, const float* __restrict__ bk,
    const float* __restrict__ Wv, const float* __restrict__ bv,
    const float* __restrict__ Wa1,
    float* __restrict__ qlno,
    float* __restrict__ Qo, float* __restrict__ Ko, float* __restrict__ Vo,
    float* __restrict__ uo)
{
    __shared__ float xs[16][128];
    __shared__ float Qs[16][128];
    __shared__ float ps[3][16][128];
    int t = threadIdx.x; int e = t&127; int s = t>>7; int l = t&31; int w = t>>5;
    int r0 = blockIdx.x*16;
    for(int k=t;k<2048;k+=512) xs[k>>7][k&127] = xin[(size_t)r0*Hq + k];
    __syncthreads();
    lnrow(xs[w], g1, b1, l, qlno + (size_t)(r0+w)*Hq);
    __syncthreads();

    float o16[16];
    mat16q(xs, ps, Wq, bq, e, s, o16);
    if(s==0){
        #pragma unroll
        for(int r=0;r<16;r++){ float v=o16[r]; Qo[(size_t)(r0+r)*Hq+e]=v; Qs[r][e]=v; }
    }
    mat16q(xs, ps, Wk, bk, e, s, o16);
    if(s==0){
        #pragma unroll
        for(int r=0;r<16;r++) Ko[(size_t)(r0+r)*Hq+e]=o16[r];
    }
    mat16q(xs, ps, Wv, bv, e, s, o16);
    if(s==0){
        #pragma unroll
        for(int r=0;r<16;r++) Vo[(size_t)(r0+r)*Hq+e]=o16[r];
    }
    __syncthreads();

    // u[row][h][c] = sum_d WA1[h*32+d, c] * Q[row, h*32+d];  thread=(h=s, c=e)
    int h = s, c = e;
    unsigned long long ua[16];
    #pragma unroll
    for(int r=0;r<16;r++) ua[r]=0ULL;
    const float* wbase = Wa1 + c;
    #pragma unroll 4
    for(int d=0; d<32; d+=2){
        float wa = wbase[(size_t)(h*32+d)*128];
        float wb = wbase[(size_t)(h*32+d+1)*128];
        unsigned long long w2; asm("mov.b64 %0, {%1,%2};" : "=l"(w2) : "f"(wa), "f"(wb));
        #pragma unroll
        for(int r=0;r<16;r++){
            unsigned long long q2 = *(const unsigned long long*)(&Qs[r][h*32+d]);
            ffma2(ua[r], w2, q2);
        }
    }
    #pragma unroll
    for(int r=0;r<16;r++)
        uo[((size_t)(r0+r)*4 + h)*128 + c] = ullsum(ua[r]);
}

// ---------------- k_qk: qk[row][h][j] = Q_h[b,i] . K_h[b,j] ----------------
__global__ void __launch_bounds__(256) k_qk(const float* __restrict__ Qp,
                                            const float* __restrict__ Kp,
                                            float* __restrict__ qko){
    __shared__ float Qsh[64*33];
    __shared__ float Ksh[64*33];
    int bid = blockIdx.x;
    int jt = bid&3, it = (bid>>2)&3, h = (bid>>4)&3, b = bid>>6;
    int t = threadIdx.x;
    int i0 = it*64, j0 = jt*64;
    for(int k=t;k<2048;k+=256){
        int rr=k>>5, dd=k&31;
        Qsh[rr*33+dd] = Qp[((size_t)(b*256+i0+rr))*128 + h*32+dd];
        Ksh[rr*33+dd] = Kp[((size_t)(b*256+j0+rr))*128 + h*32+dd];
    }
    __syncthreads();
    int i4 = (t>>4)<<2, j4 = (t&15)<<2;
    float acc[4][4];
    #pragma unroll
    for(int a=0;a<4;a++)
        #pragma unroll
        for(int bb=0;bb<4;bb++) acc[a][bb]=0.f;
    #pragma unroll 4
    for(int d=0; d<32; d++){
        float q0=Qsh[(i4+0)*33+d], q1=Qsh[(i4+1)*33+d], q2=Qsh[(i4+2)*33+d], q3=Qsh[(i4+3)*33+d];
        float k0=Ksh[(j4+0)*33+d], k1=Ksh[(j4+1)*33+d], k2=Ksh[(j4+2)*33+d], k3=Ksh[(j4+3)*33+d];
        acc[0][0]+=q0*k0; acc[0][1]+=q0*k1; acc[0][2]+=q0*k2; acc[0][3]+=q0*k3;
        acc[1][0]+=q1*k0; acc[1][1]+=q1*k1; acc[1][2]+=q1*k2; acc[1][3]+=q1*k3;
        acc[2][0]+=q2*k0; acc[2][1]+=q2*k1; acc[2][2]+=q2*k2; acc[2][3]+=q2*k3;
        acc[3][0]+=q3*k0; acc[3][1]+=q3*k1; acc[3][2]+=q3*k2; acc[3][3]+=q3*k3;
    }
    #pragma unroll
    for(int ii=0;ii<4;ii++){
        size_t base = ((size_t)(b*256 + i0+i4+ii)*4 + h)*256 + j0 + j4;
        *(float4*)(qko + base) = make_float4(acc[ii][0],acc[ii][1],acc[ii][2],acc[ii][3]);
    }
}

// ---------------- fused flash attention: one CTA per (b,i) ----------------
// floats: buf 2x8192 | qks 2x256 | u 512 | s4 1024 (reused: t_s 512 + red 128) |
//         sc_w 256 | alph 4 | sinv 4
#define ATTN_FLOATS (16384 + 512 + 512 + 1024 + 256 + 8)
#define ATTN_SMEM (ATTN_FLOATS*4)
__global__ void __launch_bounds__(256) k_attn(
    const float* __restrict__ tm,  const float* __restrict__ qln,
    const float* __restrict__ Vp,  const float* __restrict__ up,
    const float* __restrict__ qkg, const unsigned char* __restrict__ msk,
    const float* __restrict__ Wa2, float* __restrict__ xo)
{
    extern __shared__ float sm[];
    float* qks  = sm + 16384;   // 2 x 256
    float* u_s  = sm + 16896;   // 512
    float* s4   = sm + 17408;   // 1024
    float* sc_w = sm + 18432;   // 256
    float* alph = sm + 18688;
    float* sinv = sm + 18692;
    float* t_s  = s4;           // epilogue reuse
    float* red  = s4 + 512;

    int t = threadIdx.x, l = t&31, w = t>>5;
    int r = blockIdx.x, b = r>>8;
    int i = 255 - (r&255);               // heavy rows first
    int rr = (b<<8) + i;
    bool rowmask = msk[rr] != 0;
    int nj  = rowmask ? 256 : (i+1);
    int nch = (nj + 63) >> 6;

    // ---- prologue: u row + chunk0 tm (swizzled) + chunk0 qk ----
    if(t < 128) cpa16(u_s + t*4, up + (size_t)rr*512 + t*4);
    {
        int jn = nj < 64 ? nj : 64;
        const float* src = tm + (size_t)rr*32768;
        for(int k=t;k<jn*32;k+=256){
            int jr=k>>5, c4=k&31;
            cpa16(sm + jr*128 + ((c4 ^ (jr&7))<<2), src + 4*k);
        }
        if(t<64){
            int hh=t>>4, qi=t&15;
            cpa16(qks + hh*64 + qi*4, qkg + ((size_t)rr*4 + hh)*256 + qi*4);
        }
        for(int k=t;k<(64-jn)*32;k+=256)
            *(float4*)(sm + (jn+(k>>5))*128 + (k&31)*4) = make_float4(0.f,0.f,0.f,0.f);
    }
    asm volatile("cp.async.commit_group;\n"::);

    int qA = t>>6, jA = t&63;            // phase A: c-quarter x j
    int eO = t&127, jhO = t>>7, hO = (t&127)>>5; // phase O: elem x j-half

    float tacc[4][4];
    #pragma unroll
    for(int a=0;a<4;a++)
        #pragma unroll
        for(int bb=0;bb<4;bb++) tacc[a][bb]=0.f;
    float oacc = 0.f;
    float m_run = -3.402823466e38f, s_run = 0.f;
    const float NEGV = -4294967295.0f;
    const float SCL  = 0.17677669529663689f;

    for(int c=0;c<nch;c++){
        int cb = c&1;
        if(c+1 < nch){
            int nb = cb^1;
            int j0n = (c+1)<<6;
            int jn = nj - j0n; if(jn>64) jn=64;
            const float* src = tm + (size_t)rr*32768 + (size_t)j0n*128;
            float* dst = sm + nb*8192;
            for(int k=t;k<jn*32;k+=256){
                int jr=k>>5, c4=k&31;
                cpa16(dst + jr*128 + ((c4 ^ (jr&7))<<2), src + 4*k);
            }
            if(t<64){
                int hh=t>>4, qi=t&15;
                cpa16(qks + nb*256 + hh*64 + qi*4,
                      qkg + ((size_t)rr*4 + hh)*256 + j0n + qi*4);
            }
            for(int k=t;k<(64-jn)*32;k+=256)
                *(float4*)(dst + (jn+(k>>5))*128 + (k&31)*4) = make_float4(0.f,0.f,0.f,0.f);
            asm volatile("cp.async.commit_group;\n"::);
            asm volatile("cp.async.wait_group 1;\n"::);
        } else {
            asm volatile("cp.async.wait_group 0;\n"::);
        }
        __syncthreads();
        const float* bufc = sm + cb*8192;
        int j0 = c<<6;

        // ---- phase A: partial scores over c-quarter qA for row jA (no shuffles)
        {
            const float* base = bufc + jA*128;
            int sw = jA&7;
            float a0=0.f,a1=0.f,a2=0.f,a3=0.f;
            #pragma unroll
            for(int cq=0;cq<8;cq++){
                int c4 = qA*8+cq;
                float4 tv = *(const float4*)(base + ((c4 ^ sw)<<2));
                float4 u0 = *(const float4*)(u_s +        c4*4);
                float4 u1 = *(const float4*)(u_s + 128 +  c4*4);
                float4 u2 = *(const float4*)(u_s + 256 +  c4*4);
                float4 u3 = *(const float4*)(u_s + 384 +  c4*4);
                a0 += u0.x*tv.x + u0.y*tv.y + u0.z*tv.z + u0.w*tv.w;
                a1 += u1.x*tv.x + u1.y*tv.y + u1.z*tv.z + u1.w*tv.w;
                a2 += u2.x*tv.x + u2.y*tv.y + u2.z*tv.z + u2.w*tv.w;
                a3 += u3.x*tv.x + u3.y*tv.y + u3.z*tv.z + u3.w*tv.w;
            }
            s4[(qA*4+0)*64 + jA] = a0;
            s4[(qA*4+1)*64 + jA] = a1;
            s4[(qA*4+2)*64 + jA] = a2;
            s4[(qA*4+3)*64 + jA] = a3;
        }
        __syncthreads();

        // ---- phase B: reduce + online softmax (warp w = head w) ----
        if(w<4){
            float r0 = (s4[(0*4+w)*64+l] + s4[(1*4+w)*64+l] +
                        s4[(2*4+w)*64+l] + s4[(3*4+w)*64+l] +
                        qks[cb*256 + w*64 + l]) * SCL;
            float r1 = (s4[(0*4+w)*64+32+l] + s4[(1*4+w)*64+32+l] +
                        s4[(2*4+w)*64+32+l] + s4[(3*4+w)*64+32+l] +
                        qks[cb*256 + w*64 + 32 + l]) * SCL;
            bool v0 = ((j0 + l)      < nj) && !rowmask;
            bool v1 = ((j0 + 32 + l) < nj) && !rowmask;
            r0 = v0 ? r0 : NEGV;
            r1 = v1 ? r1 : NEGV;
            float mx = fmaxf(r0, r1);
            #pragma unroll
            for(int o=16;o;o>>=1) mx = fmaxf(mx, __shfl_xor_sync(0xffffffffu,mx,o));
            float mnew = fmaxf(m_run, mx);
            float alpha = __expf(m_run - mnew);
            float e0 = __expf(r0 - mnew), e1 = __expf(r1 - mnew);
            float cs = e0 + e1;
            #pragma unroll
            for(int o=16;o;o>>=1) cs += __shfl_xor_sync(0xffffffffu,cs,o);
            s_run = s_run*alpha + cs;
            m_run = mnew;
            sc_w[w*64 + l]      = e0;
            sc_w[w*64 + 32 + l] = e1;
            if(l==0) alph[w] = alpha;
        }
        __syncthreads();

        // ---- phase C: tacc[h][cc] over j-octant w at float4-column l ----
        {
            float aa0=alph[0], aa1=alph[1], aa2=alph[2], aa3=alph[3];
            #pragma unroll
            for(int cc=0;cc<4;cc++){
                tacc[0][cc]*=aa0; tacc[1][cc]*=aa1;
                tacc[2][cc]*=aa2; tacc[3][cc]*=aa3;
            }
            #pragma unroll
            for(int jj=0;jj<8;jj++){
                int j = w*8 + jj;
                float4 tv = *(const float4*)(bufc + j*128 + ((l ^ jj)<<2));
                float w0=sc_w[j], w1=sc_w[64+j], w2=sc_w[128+j], w3=sc_w[192+j];
                tacc[0][0]+=w0*tv.x; tacc[0][1]+=w0*tv.y; tacc[0][2]+=w0*tv.z; tacc[0][3]+=w0*tv.w;
                tacc[1][0]+=w1*tv.x; tacc[1][1]+=w1*tv.y; tacc[1][2]+=w1*tv.z; tacc[1][3]+=w1*tv.w;
                tacc[2][0]+=w2*tv.x; tacc[2][1]+=w2*tv.y; tacc[2][2]+=w2*tv.z; tacc[2][3]+=w2*tv.w;
                tacc[3][0]+=w3*tv.x; tacc[3][1]+=w3*tv.y; tacc[3][2]+=w3*tv.z; tacc[3][3]+=w3*tv.w;
            }
        }
        // ---- phase O: w@V partials; thread (eO, j-half jhO), all 256 threads ----
        {
            oacc *= alph[hO];
            const float* Vb = Vp + (((size_t)b<<8) + j0 + jhO*32)*128 + eO;
            const float* wp = sc_w + hO*64 + jhO*32;
            #pragma unroll 8
            for(int jj=0;jj<32;jj++)
                oacc += wp[jj] * __ldg(Vb + jj*128);
        }
        __syncthreads();
    }

    // ---- epilogue ----
    if(w<4 && l==0) sinv[w] = 1.0f / s_run;
    if(jhO==1) red[eO] = oacc;
    float* P = sm;  // tm buffers dead: 8-way tacc reduction scratch
    #pragma unroll
    for(int h=0;h<4;h++)
        *(float4*)(P + w*512 + h*128 + l*4) =
            make_float4(tacc[h][0], tacc[h][1], tacc[h][2], tacc[h][3]);
    __syncthreads();
    if(t<128){
        int h = t>>5, cq = t&31;
        float4 acc = make_float4(0.f,0.f,0.f,0.f);
        #pragma unroll
        for(int g=0;g<8;g++){
            float4 p = *(const float4*)(P + g*512 + h*128 + cq*4);
            acc.x+=p.x; acc.y+=p.y; acc.z+=p.z; acc.w+=p.w;
        }
        float sv = sinv[h];
        *(float4*)(t_s + h*128 + cq*4) =
            make_float4(acc.x*sv, acc.y*sv, acc.z*sv, acc.w*sv);
    }
    __syncthreads();
    if(t<128){
        float o = (oacc + red[eO]) * sinv[hO];
        const float4* w2 = (const float4*)(Wa2 + (size_t)eO*128);
        const float4* th = (const float4*)(t_s + hO*128);
        #pragma unroll
        for(int cq=0;cq<32;cq++){
            float4 a=w2[cq], tv=th[cq];
            o += a.x*tv.x + a.y*tv.y + a.z*tv.z + a.w*tv.w;
        }
        xo[(size_t)rr*128 + eO] = qln[(size_t)rr*128 + eO] + o;
    }
}

// ------- k_ffn: LN2 + FFN + residual + mask (+ optional fused final LN) -------
__global__ void __launch_bounds__(512) k_ffn(
    const float* __restrict__ attin,
    const float* __restrict__ g2, const float* __restrict__ b2g,
    const float* __restrict__ W1, const float* __restrict__ b1,
    const float* __restrict__ W2, const float* __restrict__ b2,
    const unsigned char* __restrict__ msk, float* __restrict__ xo,
    const float* __restrict__ lnfg, const float* __restrict__ lnfb)
{
    __shared__ float xs[16][128];
    __shared__ float hs[16][128];
    __shared__ float ps[3][16][128];
    int t = threadIdx.x; int e = t&127; int s = t>>7; int l = t&31; int w = t>>5;
    int r0 = blockIdx.x*16;
    for(int k=t;k<2048;k+=512) xs[k>>7][k&127] = attin[(size_t)r0*Hq + k];
    __syncthreads();
    lnrow(xs[w], g2, b2g, l, (float*)0);
    __syncthreads();

    float o16[16];
    mat16q(xs, ps, W1, b1, e, s, o16);
    if(s==0){
        #pragma unroll
        for(int r=0;r<16;r++) hs[r][e] = fmaxf(o16[r], 0.f);
    }
    __syncthreads();
    mat16q(hs, ps, W2, b2, e, s, o16);
    if(lnfg == (const float*)0){
        if(s==0){
            #pragma unroll
            for(int r=0;r<16;r++){
                int row = r0 + r;
                float kp = msk[row] ? 0.f : 1.f;
                xo[(size_t)row*Hq + e] = (o16[r] + xs[r][e]) * kp;
            }
        }
    } else {
        if(s==0){
            #pragma unroll
            for(int r=0;r<16;r++){
                float kp = msk[r0+r] ? 0.f : 1.f;
                xs[r][e] = (o16[r] + xs[r][e]) * kp;
            }
        }
        __syncthreads();
        lnrow(xs[w], lnfg, lnfb, l, xo + (size_t)(r0+w)*Hq);
    }
}

// ---------------- launch ----------------
extern "C" void kernel_launch(void* const* d_in, const int* in_sizes, int n_in,
                              void* d_out, int out_size){
    const float* seqs = (const float*)d_in[0];
    const unsigned char* msk = (const unsigned char*)d_in[1];
    const float* tm  = (const float*)d_in[2];
    const float* Qw  = (const float*)d_in[3];
    const float* Qb  = (const float*)d_in[4];
    const float* Kw  = (const float*)d_in[5];
    const float* Kb  = (const float*)d_in[6];
    const float* Vw  = (const float*)d_in[7];
    const float* Vb  = (const float*)d_in[8];
    const float* WA1 = (const float*)d_in[9];
    const float* WA2 = (const float*)d_in[10];
    const float* ln1g= (const float*)d_in[11];
    const float* ln1b= (const float*)d_in[12];
    const float* ln2g= (const float*)d_in[13];
    const float* ln2b= (const float*)d_in[14];
    const float* c1w = (const float*)d_in[15];
    const float* c1b = (const float*)d_in[16];
    const float* c2w = (const float*)d_in[17];
    const float* c2b = (const float*)d_in[18];
    const float* lnfg= (const float*)d_in[19];
    const float* lnfb= (const float*)d_in[20];

    float *gqln,*gQ,*gK,*gV,*gu,*gqk,*gatt,*gx;
    cudaGetSymbolAddress((void**)&gqln, g_qln);
    cudaGetSymbolAddress((void**)&gQ,   g_Q);
    cudaGetSymbolAddress((void**)&gK,   g_K);
    cudaGetSymbolAddress((void**)&gV,   g_V);
    cudaGetSymbolAddress((void**)&gu,   g_u);
    cudaGetSymbolAddress((void**)&gqk,  g_qk);
    cudaGetSymbolAddress((void**)&gatt, g_att);
    cudaGetSymbolAddress((void**)&gx,   g_x);

    cudaFuncSetAttribute(k_attn, cudaFuncAttributeMaxDynamicSharedMemorySize, ATTN_SMEM);

    for(int blk=0; blk<2; blk++){
        const float* xin = blk ? (const float*)gx : seqs;
        k_proj<<<128,512>>>(xin, ln1g+blk*Hq, ln1b+blk*Hq,
                            Qw+(size_t)blk*HHq, Qb+blk*Hq,
                            Kw+(size_t)blk*HHq, Kb+blk*Hq,
                            Vw+(size_t)blk*HHq, Vb+blk*Hq,
                            WA1+(size_t)blk*HHq,
                            gqln, gQ, gK, gV, gu);
        k_qk  <<<512,256>>>(gQ, gK, gqk);
        k_attn<<<BLq,256,ATTN_SMEM>>>(tm, gqln, gV, gu, gqk, msk,
                                      WA2+(size_t)blk*HHq, gatt);
        k_ffn <<<128,512>>>(gatt, ln2g+blk*Hq, ln2b+blk*Hq,
                            c1w+(size_t)blk*HHq, c1b+blk*Hq,
                            c2w+(size_t)blk*HHq, c2b+blk*Hq, msk,
                            blk==0 ? gx : (float*)d_out,
                            blk==0 ? (const float*)0 : lnfg,
                            blk==0 ? (const float*)0 : lnfb);
    }
}